// round 8
// baseline (speedup 1.0000x reference)
#include <cuda_runtime.h>
#include <cuda_fp16.h>
#include <math.h>

#define NN 50000          // nodes
#define NE 400000         // edges (without self loops)
#define ET (NN + NE)      // total edges incl. self loops
#define NH 8              // heads
#define HC 512            // heads * channels
#define FIN 11            // input features
#define K1B ((NN + 7) / 8)                 // k1 blocks inside merged kernel
#define HISTB ((ET + 127) / 128)           // hist blocks inside merged kernel

// ---------------- scratch (static device globals; no allocation) -------------
__device__ __align__(16) __half g_hh[(size_t)NN * HC];  // layer-1 features (51 MB, fp16)
__device__ __align__(16) float g_asrc[NN * NH];
__device__ __align__(16) float g_adst[NN * NH];
__device__ __align__(16) float g_wsum[NN * NH];         // per-(dst,head) sum of exp
__device__ int   g_cnt[NN];     // zero-initialized; re-zeroed by k_offsets each call
__device__ int   g_off[NN];
__device__ int   g_qend[NN];
__device__ int   g_cur[NN];
__device__ int   g_total;       // zero-initialized; re-zeroed by k_scatter each call
__device__ int   g_ssrc[ET];
__device__ __align__(16) float g_w[(size_t)ET * NH];    // exp(edge score) (14.4 MB)
__device__ float g_h2[NN];
__device__ float g_a2s[NN];
__device__ float g_a2d[NN];

__device__ __forceinline__ float lrelu(float v) { return v > 0.f ? v : 0.2f * v; }
__device__ __forceinline__ float4 f4fma(float a, float4 v, float4 acc) {
    acc.x = fmaf(a, v.x, acc.x); acc.y = fmaf(a, v.y, acc.y);
    acc.z = fmaf(a, v.z, acc.z); acc.w = fmaf(a, v.w, acc.w); return acc;
}
__device__ __forceinline__ float f4dot(float4 a, float4 b) {
    return a.x * b.x + a.y * b.y + a.z * b.z + a.w * b.w;
}
__device__ __forceinline__ float f4get(float4 v, int k) {
    return k == 0 ? v.x : k == 1 ? v.y : k == 2 ? v.z : v.w;
}
__device__ __forceinline__ int edge_at(const void* ei, int idx, int is64) {
    return is64 ? (int)((const long long*)ei)[idx] : ((const int*)ei)[idx];
}
// block-local edge dtype detection (int32 vs int64), broadcast via smem.
// For int32 data, an int64 read of two node ids is >= 2^32 unless the high
// word is 0 (P ~ 2e-5 per element); 8 checks make a false positive ~0.
__device__ __forceinline__ int detect_is64(const void* ei, int nNodes, int* sflag) {
    if (threadIdx.x == 0) {
        const long long* p = (const long long*)ei;
        int ok = 1;
#pragma unroll 1
        for (int k = 0; k < 8; k++) {
            long long v = p[k];
            if (v < 0 || v >= nNodes) { ok = 0; break; }
        }
        *sflag = ok;
    }
    __syncthreads();
    return *sflag;
}
__device__ __forceinline__ void fma8(float w, uint4 v, float* acc) {
    const __half2* h = (const __half2*)&v;
#pragma unroll
    for (int k = 0; k < 4; k++) {
        float2 f = __half22float2(h[k]);
        acc[2 * k]     = fmaf(w, f.x, acc[2 * k]);
        acc[2 * k + 1] = fmaf(w, f.y, acc[2 * k + 1]);
    }
}

// ---------------- K1: feature transform | degree histogram (merged) ----------
// Blocks [0, K1B): h = x@W1 -> fp16, a_src, a_dst (8 nodes/block, 128 thr).
// Blocks [K1B, K1B+HISTB): histogram of dst degrees (128 edges/block).
__global__ void k1_hist(const float* __restrict__ x, const float* __restrict__ W1,
                        const float* __restrict__ as1, const float* __restrict__ ad1,
                        const void* __restrict__ ei, int nNodes, int nE) {
    __shared__ float sx[8][FIN];
    __shared__ int sflag;
    int t = threadIdx.x;
    if (blockIdx.x >= K1B) {                 // ---- histogram role ----
        int is64 = detect_is64(ei, nNodes, &sflag);
        int i = (blockIdx.x - K1B) * 128 + t;
        int tot = nE + nNodes;
        if (i >= tot) return;
        int d = (i < nE) ? edge_at(ei, nE + i, is64) : (i - nE);
        if ((unsigned)d >= (unsigned)nNodes) return;
        atomicAdd(&g_cnt[d], 1);
        return;
    }
    // ---- k1 role ----
    int nb = blockIdx.x * 8;
    if (t < 8 * FIN) {
        int ni = t / FIN, k = t % FIN;
        int n = nb + ni;
        sx[ni][k] = (n < nNodes) ? x[(size_t)n * FIN + k] : 0.f;
    }
    float4 w[FIN];
#pragma unroll
    for (int k = 0; k < FIN; k++) w[k] = ((const float4*)W1)[k * 128 + t];
    float4 a4 = ((const float4*)as1)[t];
    float4 d4 = ((const float4*)ad1)[t];
    __syncthreads();
    int head = t >> 4;  // 16 threads per head
#pragma unroll 1
    for (int ni = 0; ni < 8; ni++) {
        int n = nb + ni;
        if (n >= nNodes) break;
        float4 acc = {0.f, 0.f, 0.f, 0.f};
#pragma unroll
        for (int k = 0; k < FIN; k++) acc = f4fma(sx[ni][k], w[k], acc);
        union { __half2 h2[2]; uint2 u; } pk;
        pk.h2[0] = __floats2half2_rn(acc.x, acc.y);
        pk.h2[1] = __floats2half2_rn(acc.z, acc.w);
        ((uint2*)g_hh)[(size_t)n * 128 + t] = pk.u;
        float ps = f4dot(acc, a4);
        float pd = f4dot(acc, d4);
#pragma unroll
        for (int o = 8; o >= 1; o >>= 1) {
            ps += __shfl_xor_sync(0xffffffffu, ps, o);
            pd += __shfl_xor_sync(0xffffffffu, pd, o);
        }
        if ((t & 15) == 0) {
            g_asrc[n * NH + head] = ps;
            g_adst[n * NH + head] = pd;
        }
    }
}

// ---------------- K2: offsets via warp-aggregated atomic bump ----------------
// Also re-zeroes g_cnt and g_wsum for the next graph replay.
__global__ void k_offsets(int nNodes) {
    int n = blockIdx.x * blockDim.x + threadIdx.x;
    int lane = threadIdx.x & 31;
    int c = (n < nNodes) ? g_cnt[n] : 0;
    int incl = c;
#pragma unroll
    for (int o = 1; o < 32; o <<= 1) {
        int v = __shfl_up_sync(0xffffffffu, incl, o);
        if (lane >= o) incl += v;
    }
    int wtot = __shfl_sync(0xffffffffu, incl, 31);
    int base = 0;
    if (lane == 31) base = atomicAdd(&g_total, wtot);
    base = __shfl_sync(0xffffffffu, base, 31);
    if (n < nNodes) {
        int start = base + incl - c;
        g_off[n]  = start;
        g_qend[n] = start + c;
        g_cur[n]  = start;
        g_cnt[n]  = 0;                       // reset for next replay
        float4 z = {0.f, 0.f, 0.f, 0.f};
        ((float4*)&g_wsum[n * NH])[0] = z;   // zero softmax sums for scatter
        ((float4*)&g_wsum[n * NH])[1] = z;
    }
}

// ---------------- K3: scatter sorted edges + exp scores + atomic head sums ---
__global__ void k_scatter(const void* __restrict__ ei, int nE, int nNodes) {
    __shared__ int sflag;
    int is64 = detect_is64(ei, nNodes, &sflag);
    if (blockIdx.x == 0 && threadIdx.x == 0) g_total = 0;   // reset for next replay
    int i = blockIdx.x * blockDim.x + threadIdx.x;
    int tot = nE + nNodes;
    if (i >= tot) return;
    int s, d;
    if (i < nE) { s = edge_at(ei, i, is64); d = edge_at(ei, nE + i, is64); }
    else        { s = d = i - nE; }
    if ((unsigned)d >= (unsigned)nNodes || (unsigned)s >= (unsigned)nNodes) return;
    int pos = atomicAdd(&g_cur[d], 1);
    g_ssrc[pos] = s;
    float4 a0 = ((const float4*)&g_asrc[s * NH])[0];
    float4 a1 = ((const float4*)&g_asrc[s * NH])[1];
    float4 d0 = ((const float4*)&g_adst[d * NH])[0];
    float4 d1 = ((const float4*)&g_adst[d * NH])[1];
    float4 e0, e1;
    e0.x = __expf(lrelu(a0.x + d0.x)); e0.y = __expf(lrelu(a0.y + d0.y));
    e0.z = __expf(lrelu(a0.z + d0.z)); e0.w = __expf(lrelu(a0.w + d0.w));
    e1.x = __expf(lrelu(a1.x + d1.x)); e1.y = __expf(lrelu(a1.y + d1.y));
    e1.z = __expf(lrelu(a1.z + d1.z)); e1.w = __expf(lrelu(a1.w + d1.w));
    ((float4*)&g_w[(size_t)pos * NH])[0] = e0;
    ((float4*)&g_w[(size_t)pos * NH])[1] = e1;
    float* ws = &g_wsum[d * NH];
    atomicAdd(ws + 0, e0.x); atomicAdd(ws + 1, e0.y);
    atomicAdd(ws + 2, e0.z); atomicAdd(ws + 3, e0.w);
    atomicAdd(ws + 4, e1.x); atomicAdd(ws + 5, e1.y);
    atomicAdd(ws + 6, e1.z); atomicAdd(ws + 7, e1.w);
}

// ---------------- K4: aggregation (1 warp/node, single gather loop) ----------
// Lane L owns channels [8L,8L+8) (head L>>3) and [256+8L,+8) (head (L>>3)+4).
// Softmax sums come precomputed from k_scatter's atomics: one 32B read/node.
__global__ void k_agg(const float* __restrict__ b1, const float* __restrict__ W2,
                      const float* __restrict__ as2, const float* __restrict__ ad2,
                      int nNodes) {
    int n = (blockIdx.x * blockDim.x + threadIdx.x) >> 5;
    int lane = threadIdx.x & 31;
    if (n >= nNodes) return;
    int p = g_off[n], q = g_qend[n];

    float4 s0 = ((const float4*)&g_wsum[n * NH])[0];
    float4 s1 = ((const float4*)&g_wsum[n * NH])[1];
    int hA = lane >> 3;                       // 0..3
    float iA = 1.f / (f4get(s0, hA) + 1e-16f);
    float iB = 1.f / (f4get(s1, hA) + 1e-16f);

    // weighted gather of fp16 h[src] rows (hot loop, unroll x2)
    float accA[8], accB[8];
#pragma unroll
    for (int k = 0; k < 8; k++) { accA[k] = 0.f; accB[k] = 0.f; }
    int i = p;
#pragma unroll 1
    for (; i + 2 <= q; i += 2) {
        int sn0 = g_ssrc[i];
        int sn1 = g_ssrc[i + 1];
        float wA0 = g_w[(size_t)i * NH + hA];
        float wB0 = g_w[(size_t)i * NH + hA + 4];
        float wA1 = g_w[(size_t)(i + 1) * NH + hA];
        float wB1 = g_w[(size_t)(i + 1) * NH + hA + 4];
        const uint4* h0 = (const uint4*)&g_hh[(size_t)sn0 * HC];
        const uint4* h1 = (const uint4*)&g_hh[(size_t)sn1 * HC];
        uint4 vA0 = h0[lane];
        uint4 vB0 = h0[lane + 32];
        uint4 vA1 = h1[lane];
        uint4 vB1 = h1[lane + 32];
        fma8(wA0 * iA, vA0, accA);
        fma8(wB0 * iB, vB0, accB);
        fma8(wA1 * iA, vA1, accA);
        fma8(wB1 * iB, vB1, accB);
    }
    if (i < q) {
        int sn = g_ssrc[i];
        float wA = g_w[(size_t)i * NH + hA];
        float wB = g_w[(size_t)i * NH + hA + 4];
        const uint4* hr = (const uint4*)&g_hh[(size_t)sn * HC];
        uint4 vA = hr[lane];
        uint4 vB = hr[lane + 32];
        fma8(wA * iA, vA, accA);
        fma8(wB * iB, vB, accB);
    }

    // epilogue: + b1, ELU, project with W2, warp-reduce -> h2 scalar
    float dot = 0.f;
#pragma unroll
    for (int k = 0; k < 8; k++) {
        float vA = accA[k] + b1[8 * lane + k];
        vA = vA > 0.f ? vA : __expf(vA) - 1.f;
        dot = fmaf(vA, W2[8 * lane + k], dot);
        float vB = accB[k] + b1[256 + 8 * lane + k];
        vB = vB > 0.f ? vB : __expf(vB) - 1.f;
        dot = fmaf(vB, W2[256 + 8 * lane + k], dot);
    }
#pragma unroll
    for (int o = 16; o; o >>= 1) dot += __shfl_xor_sync(0xffffffffu, dot, o);
    if (lane == 0) {
        g_h2[n]  = dot;
        g_a2s[n] = dot * as2[0];
        g_a2d[n] = dot * ad2[0];
    }
}

// ---------------- K5: layer-2 attention (warp per node, single pass) ---------
__global__ void k_l2(float* __restrict__ out, const float* __restrict__ b2, int nNodes) {
    int n = (blockIdx.x * blockDim.x + threadIdx.x) >> 5;
    int lane = threadIdx.x & 31;
    if (n >= nNodes) return;
    int p = g_off[n], q = g_qend[n];
    float ad = g_a2d[n];
    float sum = 0.f, acc = 0.f;
    for (int i = p + lane; i < q; i += 32) {
        int sn = g_ssrc[i];
        float v = __expf(lrelu(g_a2s[sn] + ad));
        sum += v;
        acc = fmaf(v, g_h2[sn], acc);
    }
#pragma unroll
    for (int o = 16; o; o >>= 1) {
        sum += __shfl_xor_sync(0xffffffffu, sum, o);
        acc += __shfl_xor_sync(0xffffffffu, acc, o);
    }
    if (lane == 0) out[n] = acc / (sum + 1e-16f) + b2[0];
}

// ---------------- launch -----------------------------------------------------
extern "C" void kernel_launch(void* const* d_in, const int* in_sizes, int n_in,
                              void* d_out, int out_size) {
    const float* x   = (const float*)d_in[0];
    const void*  ei  = d_in[1];
    const float* W1  = (const float*)d_in[2];
    const float* as1 = (const float*)d_in[3];
    const float* ad1 = (const float*)d_in[4];
    const float* b1  = (const float*)d_in[5];
    const float* W2  = (const float*)d_in[6];
    const float* as2 = (const float*)d_in[7];
    const float* ad2 = (const float*)d_in[8];
    const float* b2  = (const float*)d_in[9];

    int nN = in_sizes[0] / FIN;   // 50000
    int nE = in_sizes[1] / 2;     // 400000
    int tot = nN + nE;

    k1_hist  <<<K1B + HISTB, 128>>>(x, W1, as1, ad1, ei, nN, nE);
    k_offsets<<<(nN + 255) / 256, 256>>>(nN);
    k_scatter<<<(tot + 255) / 256, 256>>>(ei, nE, nN);
    k_agg    <<<(nN + 7) / 8, 256>>>(b1, W2, as2, ad2, nN);
    k_l2     <<<(nN + 7) / 8, 256>>>((float*)d_out, b2, nN);
}

// round 9
// speedup vs baseline: 1.1765x; 1.1765x over previous
#include <cuda_runtime.h>
#include <cuda_fp16.h>
#include <math.h>

#define NN 50000          // nodes
#define NE 400000         // edges (without self loops)
#define ET (NN + NE)      // total edges incl. self loops
#define NH 8              // heads
#define HC 512            // heads * channels
#define FIN 11            // input features
#define K1B ((NN + 7) / 8)                 // k1 blocks inside merged kernel
#define HISTB ((ET + 127) / 128)           // hist blocks inside merged kernel

// ---------------- scratch (static device globals; no allocation) -------------
__device__ __align__(16) __half g_hh[(size_t)NN * HC];  // layer-1 features (51 MB, fp16)
__device__ __align__(16) float g_asrc[NN * NH];
__device__ __align__(16) float g_adst[NN * NH];
__device__ int   g_cnt[NN];     // zero-initialized; re-zeroed by k_offsets each call
__device__ int   g_off[NN];
__device__ int   g_qend[NN];
__device__ int   g_cur[NN];
__device__ int   g_total;       // zero-initialized; re-zeroed by k_scatter each call
__device__ int   g_ssrc[ET];
__device__ __align__(16) uint4 g_wp[ET];   // 8 x fp16 unnormalized exp weights (7.2 MB)
__device__ float g_h2[NN];
__device__ float g_a2s[NN];
__device__ float g_a2d[NN];

__device__ __forceinline__ float lrelu(float v) { return v > 0.f ? v : 0.2f * v; }
__device__ __forceinline__ float4 f4fma(float a, float4 v, float4 acc) {
    acc.x = fmaf(a, v.x, acc.x); acc.y = fmaf(a, v.y, acc.y);
    acc.z = fmaf(a, v.z, acc.z); acc.w = fmaf(a, v.w, acc.w); return acc;
}
__device__ __forceinline__ float f4dot(float4 a, float4 b) {
    return a.x * b.x + a.y * b.y + a.z * b.z + a.w * b.w;
}
__device__ __forceinline__ int edge_at(const void* ei, int idx, int is64) {
    return is64 ? (int)((const long long*)ei)[idx] : ((const int*)ei)[idx];
}
// block-local edge dtype detection (int32 vs int64), broadcast via smem.
__device__ __forceinline__ int detect_is64(const void* ei, int nNodes, int* sflag) {
    if (threadIdx.x == 0) {
        const long long* p = (const long long*)ei;
        int ok = 1;
#pragma unroll 1
        for (int k = 0; k < 8; k++) {
            long long v = p[k];
            if (v < 0 || v >= nNodes) { ok = 0; break; }
        }
        *sflag = ok;
    }
    __syncthreads();
    return *sflag;
}
__device__ __forceinline__ void fma8(float w, uint4 v, float* acc) {
    const __half2* h = (const __half2*)&v;
#pragma unroll
    for (int k = 0; k < 4; k++) {
        float2 f = __half22float2(h[k]);
        acc[2 * k]     = fmaf(w, f.x, acc[2 * k]);
        acc[2 * k + 1] = fmaf(w, f.y, acc[2 * k + 1]);
    }
}
// extract fp16 weight h (0..7) from packed uint4; wsel = h>>1 selector done by caller
__device__ __forceinline__ float wext(unsigned word, int hsh) {
    return __half2float(__ushort_as_half((unsigned short)(word >> hsh)));
}

// ---------------- K1: feature transform | degree histogram (merged) ----------
__global__ void k1_hist(const float* __restrict__ x, const float* __restrict__ W1,
                        const float* __restrict__ as1, const float* __restrict__ ad1,
                        const void* __restrict__ ei, int nNodes, int nE) {
    __shared__ float sx[8][FIN];
    __shared__ int sflag;
    int t = threadIdx.x;
    if (blockIdx.x >= K1B) {                 // ---- histogram role ----
        int is64 = detect_is64(ei, nNodes, &sflag);
        int i = (blockIdx.x - K1B) * 128 + t;
        int tot = nE + nNodes;
        if (i >= tot) return;
        int d = (i < nE) ? edge_at(ei, nE + i, is64) : (i - nE);
        if ((unsigned)d >= (unsigned)nNodes) return;
        atomicAdd(&g_cnt[d], 1);
        return;
    }
    // ---- k1 role ----
    int nb = blockIdx.x * 8;
    if (t < 8 * FIN) {
        int ni = t / FIN, k = t % FIN;
        int n = nb + ni;
        sx[ni][k] = (n < nNodes) ? x[(size_t)n * FIN + k] : 0.f;
    }
    float4 w[FIN];
#pragma unroll
    for (int k = 0; k < FIN; k++) w[k] = ((const float4*)W1)[k * 128 + t];
    float4 a4 = ((const float4*)as1)[t];
    float4 d4 = ((const float4*)ad1)[t];
    __syncthreads();
    int head = t >> 4;  // 16 threads per head
#pragma unroll 1
    for (int ni = 0; ni < 8; ni++) {
        int n = nb + ni;
        if (n >= nNodes) break;
        float4 acc = {0.f, 0.f, 0.f, 0.f};
#pragma unroll
        for (int k = 0; k < FIN; k++) acc = f4fma(sx[ni][k], w[k], acc);
        union { __half2 h2[2]; uint2 u; } pk;
        pk.h2[0] = __floats2half2_rn(acc.x, acc.y);
        pk.h2[1] = __floats2half2_rn(acc.z, acc.w);
        ((uint2*)g_hh)[(size_t)n * 128 + t] = pk.u;
        float ps = f4dot(acc, a4);
        float pd = f4dot(acc, d4);
#pragma unroll
        for (int o = 8; o >= 1; o >>= 1) {
            ps += __shfl_xor_sync(0xffffffffu, ps, o);
            pd += __shfl_xor_sync(0xffffffffu, pd, o);
        }
        if ((t & 15) == 0) {
            g_asrc[n * NH + head] = ps;
            g_adst[n * NH + head] = pd;
        }
    }
}

// ---------------- K2: offsets via warp-aggregated atomic bump ----------------
__global__ void k_offsets(int nNodes) {
    int n = blockIdx.x * blockDim.x + threadIdx.x;
    int lane = threadIdx.x & 31;
    int c = (n < nNodes) ? g_cnt[n] : 0;
    int incl = c;
#pragma unroll
    for (int o = 1; o < 32; o <<= 1) {
        int v = __shfl_up_sync(0xffffffffu, incl, o);
        if (lane >= o) incl += v;
    }
    int wtot = __shfl_sync(0xffffffffu, incl, 31);
    int base = 0;
    if (lane == 31) base = atomicAdd(&g_total, wtot);
    base = __shfl_sync(0xffffffffu, base, 31);
    if (n < nNodes) {
        int start = base + incl - c;
        g_off[n]  = start;
        g_qend[n] = start + c;
        g_cur[n]  = start;
        g_cnt[n]  = 0;                       // reset for next replay
    }
}

// ---------------- K3: scatter sorted edges + packed fp16 exp scores ----------
__global__ void k_scatter(const void* __restrict__ ei, int nE, int nNodes) {
    __shared__ int sflag;
    int is64 = detect_is64(ei, nNodes, &sflag);
    if (blockIdx.x == 0 && threadIdx.x == 0) g_total = 0;   // reset for next replay
    int i = blockIdx.x * blockDim.x + threadIdx.x;
    int tot = nE + nNodes;
    if (i >= tot) return;
    int s, d;
    if (i < nE) { s = edge_at(ei, i, is64); d = edge_at(ei, nE + i, is64); }
    else        { s = d = i - nE; }
    if ((unsigned)d >= (unsigned)nNodes || (unsigned)s >= (unsigned)nNodes) return;
    int pos = atomicAdd(&g_cur[d], 1);
    g_ssrc[pos] = s;
    float4 a0 = ((const float4*)&g_asrc[s * NH])[0];
    float4 a1 = ((const float4*)&g_asrc[s * NH])[1];
    float4 d0 = ((const float4*)&g_adst[d * NH])[0];
    float4 d1 = ((const float4*)&g_adst[d * NH])[1];
    float4 e0, e1;
    e0.x = __expf(lrelu(a0.x + d0.x)); e0.y = __expf(lrelu(a0.y + d0.y));
    e0.z = __expf(lrelu(a0.z + d0.z)); e0.w = __expf(lrelu(a0.w + d0.w));
    e1.x = __expf(lrelu(a1.x + d1.x)); e1.y = __expf(lrelu(a1.y + d1.y));
    e1.z = __expf(lrelu(a1.z + d1.z)); e1.w = __expf(lrelu(a1.w + d1.w));
    union { __half2 h2[4]; uint4 u; } pk;
    pk.h2[0] = __floats2half2_rn(e0.x, e0.y);
    pk.h2[1] = __floats2half2_rn(e0.z, e0.w);
    pk.h2[2] = __floats2half2_rn(e1.x, e1.y);
    pk.h2[3] = __floats2half2_rn(e1.z, e1.w);
    g_wp[pos] = pk.u;
}

// ---------------- K4: aggregation (1 warp/node; normalize after) -------------
// Lane L owns channels [8L,8L+8) (head L>>3) and [256+8L,+8) (head (L>>3)+4).
// Per edge: 1 broadcast ssrc + 1 broadcast packed-weight uint4 + 2 .cg gathers
// (10 L1 wavefronts/edge, metadata minimized). Every lane sees every edge, so
// each lane accumulates its own head's weight sum locally; normalization is
// applied once to the accumulator: out = (sum w*h) / (sum w).
__global__ void k_agg(const float* __restrict__ b1, const float* __restrict__ W2,
                      const float* __restrict__ as2, const float* __restrict__ ad2,
                      int nNodes) {
    int n = (blockIdx.x * blockDim.x + threadIdx.x) >> 5;
    int lane = threadIdx.x & 31;
    if (n >= nNodes) return;
    int p = g_off[n], q = g_qend[n];

    int hA   = lane >> 3;            // 0..3
    int wsel = hA >> 1;              // which uint holds head hA (A in .x/.y, B in .z/.w)
    int hsh  = (hA & 1) << 4;        // 0 or 16-bit shift

    float accA[8], accB[8];
#pragma unroll
    for (int k = 0; k < 8; k++) { accA[k] = 0.f; accB[k] = 0.f; }
    float sA = 0.f, sB = 0.f;

    int i = p;
#pragma unroll 1
    for (; i + 2 <= q; i += 2) {
        uint4 wp0 = g_wp[i];
        uint4 wp1 = g_wp[i + 1];
        int sn0 = g_ssrc[i];
        int sn1 = g_ssrc[i + 1];
        float wA0 = wext(wsel ? wp0.y : wp0.x, hsh);
        float wB0 = wext(wsel ? wp0.w : wp0.z, hsh);
        float wA1 = wext(wsel ? wp1.y : wp1.x, hsh);
        float wB1 = wext(wsel ? wp1.w : wp1.z, hsh);
        const uint4* h0 = (const uint4*)&g_hh[(size_t)sn0 * HC];
        const uint4* h1 = (const uint4*)&g_hh[(size_t)sn1 * HC];
        uint4 vA0 = __ldcg(h0 + lane);
        uint4 vB0 = __ldcg(h0 + lane + 32);
        uint4 vA1 = __ldcg(h1 + lane);
        uint4 vB1 = __ldcg(h1 + lane + 32);
        sA += wA0 + wA1;
        sB += wB0 + wB1;
        fma8(wA0, vA0, accA);
        fma8(wB0, vB0, accB);
        fma8(wA1, vA1, accA);
        fma8(wB1, vB1, accB);
    }
    if (i < q) {
        uint4 wp = g_wp[i];
        int sn = g_ssrc[i];
        float wA = wext(wsel ? wp.y : wp.x, hsh);
        float wB = wext(wsel ? wp.w : wp.z, hsh);
        const uint4* hr = (const uint4*)&g_hh[(size_t)sn * HC];
        uint4 vA = __ldcg(hr + lane);
        uint4 vB = __ldcg(hr + lane + 32);
        sA += wA; sB += wB;
        fma8(wA, vA, accA);
        fma8(wB, vB, accB);
    }

    float iA = 1.f / (sA + 1e-16f);
    float iB = 1.f / (sB + 1e-16f);

    // epilogue: normalize, + b1, ELU, project with W2, warp-reduce -> h2 scalar
    float dot = 0.f;
#pragma unroll
    for (int k = 0; k < 8; k++) {
        float vA = fmaf(accA[k], iA, b1[8 * lane + k]);
        vA = vA > 0.f ? vA : __expf(vA) - 1.f;
        dot = fmaf(vA, W2[8 * lane + k], dot);
        float vB = fmaf(accB[k], iB, b1[256 + 8 * lane + k]);
        vB = vB > 0.f ? vB : __expf(vB) - 1.f;
        dot = fmaf(vB, W2[256 + 8 * lane + k], dot);
    }
#pragma unroll
    for (int o = 16; o; o >>= 1) dot += __shfl_xor_sync(0xffffffffu, dot, o);
    if (lane == 0) {
        g_h2[n]  = dot;
        g_a2s[n] = dot * as2[0];
        g_a2d[n] = dot * ad2[0];
    }
}

// ---------------- K5: layer-2 attention (warp per node, single pass) ---------
__global__ void k_l2(float* __restrict__ out, const float* __restrict__ b2, int nNodes) {
    int n = (blockIdx.x * blockDim.x + threadIdx.x) >> 5;
    int lane = threadIdx.x & 31;
    if (n >= nNodes) return;
    int p = g_off[n], q = g_qend[n];
    float ad = g_a2d[n];
    float sum = 0.f, acc = 0.f;
    for (int i = p + lane; i < q; i += 32) {
        int sn = g_ssrc[i];
        float v = __expf(lrelu(g_a2s[sn] + ad));
        sum += v;
        acc = fmaf(v, g_h2[sn], acc);
    }
#pragma unroll
    for (int o = 16; o; o >>= 1) {
        sum += __shfl_xor_sync(0xffffffffu, sum, o);
        acc += __shfl_xor_sync(0xffffffffu, acc, o);
    }
    if (lane == 0) out[n] = acc / (sum + 1e-16f) + b2[0];
}

// ---------------- launch -----------------------------------------------------
extern "C" void kernel_launch(void* const* d_in, const int* in_sizes, int n_in,
                              void* d_out, int out_size) {
    const float* x   = (const float*)d_in[0];
    const void*  ei  = d_in[1];
    const float* W1  = (const float*)d_in[2];
    const float* as1 = (const float*)d_in[3];
    const float* ad1 = (const float*)d_in[4];
    const float* b1  = (const float*)d_in[5];
    const float* W2  = (const float*)d_in[6];
    const float* as2 = (const float*)d_in[7];
    const float* ad2 = (const float*)d_in[8];
    const float* b2  = (const float*)d_in[9];

    int nN = in_sizes[0] / FIN;   // 50000
    int nE = in_sizes[1] / 2;     // 400000
    int tot = nN + nE;

    k1_hist  <<<K1B + HISTB, 128>>>(x, W1, as1, ad1, ei, nN, nE);
    k_offsets<<<(nN + 255) / 256, 256>>>(nN);
    k_scatter<<<(tot + 255) / 256, 256>>>(ei, nE, nN);
    k_agg    <<<(nN + 7) / 8, 256>>>(b1, W2, as2, ad2, nN);
    k_l2     <<<(nN + 7) / 8, 256>>>((float*)d_out, b2, nN);
}